// round 1
// baseline (speedup 1.0000x reference)
#include <cuda_runtime.h>

namespace {

constexpr int Bc = 4, Hc = 16, Lc = 2048, Dh = 64;
constexpr int BM = 64;           // q rows per CTA
constexpr int BN = 64;           // kv rows per tile
constexpr int THREADS = 128;     // 16 x 8 thread grid, each thread: 4x8 fragment
constexpr int QS = 68;           // smem row stride for Q/K/V (float4-aligned, conflict-reduced)
constexpr int SSTR = 65;         // smem row stride for S (conflict-free scatter)
constexpr int SMEM_FLOATS = 3 * BM * QS + BM * SSTR + 3 * BM;
constexpr int SMEM_BYTES = SMEM_FLOATS * (int)sizeof(float);

__global__ void __launch_bounds__(THREADS)
attn_fwd(const float* __restrict__ Q, const float* __restrict__ K,
         const float* __restrict__ V, float* __restrict__ O) {
    extern __shared__ float sm[];
    float* Qs  = sm;                    // [64][68]
    float* Ks  = Qs + BM * QS;          // [64][68]
    float* Vs  = Ks + BN * QS;          // [64][68]
    float* Ss  = Vs + BN * QS;          // [64][65]
    float* m_s = Ss + BM * SSTR;        // [64] running row max
    float* l_s = m_s + BM;              // [64] running row sum
    float* a_s = l_s + BM;              // [64] rescale factor per tile

    const int t  = threadIdx.x;
    const int tr = t >> 3;              // 0..15 -> rows 4*tr..4*tr+3
    const int tc = t & 7;               // 0..7
    const int bh = blockIdx.y;          // b*16 + h
    const int qi = (int)gridDim.x - 1 - (int)blockIdx.x;  // reversed: big tiles first
    const int q0 = qi * BM;

    const float* Qp    = Q + ((size_t)bh * Lc + q0) * Dh;
    const float* Kbase = K + (size_t)bh * Lc * Dh;
    const float* Vbase = V + (size_t)bh * Lc * Dh;

    // ---- load Q tile (coalesced float4) ----
#pragma unroll
    for (int ch = 0; ch < 8; ++ch) {
        int pos = ch * THREADS + t;      // 0..1023 float4 slots
        int r   = pos >> 4;
        int c4  = (pos & 15) << 2;
        *(float4*)(Qs + r * QS + c4) = *(const float4*)(Qp + r * Dh + c4);
    }
    if (t < BM) { m_s[t] = -1e30f; l_s[t] = 0.f; }

    float o[4][8];
#pragma unroll
    for (int i = 0; i < 4; ++i)
#pragma unroll
        for (int j = 0; j < 8; ++j) o[i][j] = 0.f;

    const float scale = 0.125f;          // 1/sqrt(64)

    for (int kv = 0; kv <= qi; ++kv) {
        // ---- load K,V tiles ----
        const float* kp = Kbase + (size_t)kv * BN * Dh;
        const float* vp = Vbase + (size_t)kv * BN * Dh;
#pragma unroll
        for (int ch = 0; ch < 8; ++ch) {
            int pos = ch * THREADS + t;
            int r   = pos >> 4;
            int c4  = (pos & 15) << 2;
            *(float4*)(Ks + r * QS + c4) = *(const float4*)(kp + r * Dh + c4);
            *(float4*)(Vs + r * QS + c4) = *(const float4*)(vp + r * Dh + c4);
        }
        __syncthreads();

        // ---- S = Q K^T (rows r=4*tr+i, cols c=tc+8*j) ----
        float s[4][8];
#pragma unroll
        for (int i = 0; i < 4; ++i)
#pragma unroll
            for (int j = 0; j < 8; ++j) s[i][j] = 0.f;

#pragma unroll
        for (int kd = 0; kd < Dh; kd += 4) {
            float4 qf[4], kf[8];
#pragma unroll
            for (int i = 0; i < 4; ++i)
                qf[i] = *(const float4*)(Qs + (4 * tr + i) * QS + kd);
#pragma unroll
            for (int j = 0; j < 8; ++j)
                kf[j] = *(const float4*)(Ks + (tc + 8 * j) * QS + kd);
#pragma unroll
            for (int i = 0; i < 4; ++i)
#pragma unroll
                for (int j = 0; j < 8; ++j) {
                    s[i][j] = fmaf(qf[i].x, kf[j].x, s[i][j]);
                    s[i][j] = fmaf(qf[i].y, kf[j].y, s[i][j]);
                    s[i][j] = fmaf(qf[i].z, kf[j].z, s[i][j]);
                    s[i][j] = fmaf(qf[i].w, kf[j].w, s[i][j]);
                }
        }

        // ---- scale + causal mask (only diagonal tile) -> Ss ----
        const bool diag = (kv == qi);
#pragma unroll
        for (int i = 0; i < 4; ++i) {
            int rrow = 4 * tr + i;
#pragma unroll
            for (int j = 0; j < 8; ++j) {
                int c = tc + 8 * j;
                float val = s[i][j] * scale;
                if (diag && c > rrow) val = -1e30f;
                Ss[rrow * SSTR + c] = val;
            }
        }
        __syncthreads();

        // ---- online softmax: one thread per row ----
        if (t < BM) {
            float* row = Ss + t * SSTR;
            float m_old = m_s[t];
            float mx = m_old;
#pragma unroll 8
            for (int j = 0; j < BN; ++j) mx = fmaxf(mx, row[j]);
            float alpha = __expf(m_old - mx);
            float l = l_s[t] * alpha;
#pragma unroll 8
            for (int j = 0; j < BN; ++j) {
                float p = __expf(row[j] - mx);
                row[j] = p;
                l += p;
            }
            m_s[t] = mx; l_s[t] = l; a_s[t] = alpha;
        }
        __syncthreads();

        // ---- O = diag(alpha) O + P V  (O cols c = tc*8+j) ----
        float al[4];
#pragma unroll
        for (int i = 0; i < 4; ++i) al[i] = a_s[4 * tr + i];
#pragma unroll
        for (int i = 0; i < 4; ++i)
#pragma unroll
            for (int j = 0; j < 8; ++j) o[i][j] *= al[i];

#pragma unroll 8
        for (int ks = 0; ks < BN; ++ks) {
            float pf[4];
#pragma unroll
            for (int i = 0; i < 4; ++i) pf[i] = Ss[(4 * tr + i) * SSTR + ks];
            float4 v0 = *(const float4*)(Vs + ks * QS + tc * 8);
            float4 v1 = *(const float4*)(Vs + ks * QS + tc * 8 + 4);
#pragma unroll
            for (int i = 0; i < 4; ++i) {
                o[i][0] = fmaf(pf[i], v0.x, o[i][0]);
                o[i][1] = fmaf(pf[i], v0.y, o[i][1]);
                o[i][2] = fmaf(pf[i], v0.z, o[i][2]);
                o[i][3] = fmaf(pf[i], v0.w, o[i][3]);
                o[i][4] = fmaf(pf[i], v1.x, o[i][4]);
                o[i][5] = fmaf(pf[i], v1.y, o[i][5]);
                o[i][6] = fmaf(pf[i], v1.z, o[i][6]);
                o[i][7] = fmaf(pf[i], v1.w, o[i][7]);
            }
        }
        __syncthreads();   // protect Ks/Vs/Ss before next tile overwrite
    }

    // ---- epilogue: normalize + merged-head layout [B, L, H*Dh] ----
    const int b = bh >> 4;
    const int h = bh & 15;
#pragma unroll
    for (int i = 0; i < 4; ++i) {
        int r = 4 * tr + i;
        float inv = 1.f / l_s[r];
        float* op = O + ((size_t)b * Lc + (q0 + r)) * (Hc * Dh) + h * Dh + tc * 8;
        float4 w0 = make_float4(o[i][0] * inv, o[i][1] * inv, o[i][2] * inv, o[i][3] * inv);
        float4 w1 = make_float4(o[i][4] * inv, o[i][5] * inv, o[i][6] * inv, o[i][7] * inv);
        *(float4*)op       = w0;
        *(float4*)(op + 4) = w1;
    }
}

}  // namespace

extern "C" void kernel_launch(void* const* d_in, const int* in_sizes, int n_in,
                              void* d_out, int out_size) {
    const float* Q = (const float*)d_in[0];
    const float* K = (const float*)d_in[1];
    const float* V = (const float*)d_in[2];
    float* Out = (float*)d_out;

    cudaFuncSetAttribute(attn_fwd, cudaFuncAttributeMaxDynamicSharedMemorySize, SMEM_BYTES);

    dim3 grid(Lc / BM, Bc * Hc);   // 32 q-tiles x 64 (b,h)
    attn_fwd<<<grid, THREADS, SMEM_BYTES>>>(Q, K, V, Out);
}

// round 2
// speedup vs baseline: 3.5340x; 3.5340x over previous
#include <cuda_runtime.h>
#include <cstdint>

namespace {

constexpr int Bc = 4, Hc = 16, Lc = 2048, Dh = 64;
constexpr int BM = 64;            // q rows per CTA (4 warps x 16)
constexpr int BN = 64;            // kv rows per tile
constexpr int THREADS = 128;
constexpr int KSTR = 68;          // Ks stride: B-frag reads bank == lane (conflict-free)
constexpr int VSTR = 72;          // Vs stride: B-frag reads bank == 8q+j (conflict-free)
constexpr int PSTR = 68;          // Ps stride: A-frag reads conflict-free
constexpr int SMEM_FLOATS = BN * KSTR + BN * VSTR + BM * PSTR;
constexpr int SMEM_BYTES = SMEM_FLOATS * (int)sizeof(float);

__device__ __forceinline__ uint32_t f2tf(float f) {
    uint32_t r;
    asm("cvt.rna.tf32.f32 %0, %1;" : "=r"(r) : "f"(f));
    return r;
}
__device__ __forceinline__ float f2tf_f(float f) {
    return __uint_as_float(f2tf(f));
}

__device__ __forceinline__ void mma_tf32(float* c, const uint32_t* a,
                                         uint32_t b0, uint32_t b1) {
    asm volatile(
        "mma.sync.aligned.m16n8k8.row.col.f32.tf32.tf32.f32 "
        "{%0,%1,%2,%3},{%4,%5,%6,%7},{%8,%9},{%0,%1,%2,%3};"
        : "+f"(c[0]), "+f"(c[1]), "+f"(c[2]), "+f"(c[3])
        : "r"(a[0]), "r"(a[1]), "r"(a[2]), "r"(a[3]), "r"(b0), "r"(b1));
}

__global__ void __launch_bounds__(THREADS)
attn_fwd(const float* __restrict__ Q, const float* __restrict__ K,
         const float* __restrict__ V, float* __restrict__ O) {
    extern __shared__ float sm[];
    float* Ks = sm;                  // [64][68] tf32-rounded
    float* Vs = Ks + BN * KSTR;      // [64][72] tf32-rounded
    float* Ps = Vs + BN * VSTR;      // [64][68] tf32-rounded P staging

    const int t = threadIdx.x;
    const int w = t >> 5;            // warp 0..3, owns q rows 16w..16w+15
    const int lane = t & 31;
    const int g = lane >> 2;         // group id 0..7 (row within frag)
    const int q = lane & 3;          // 0..3

    const int bh = blockIdx.y;
    const int qi = (int)gridDim.x - 1 - (int)blockIdx.x;  // big tiles first
    const int q0 = qi * BM;

    const float* Kb = K + (size_t)bh * Lc * Dh;
    const float* Vb = V + (size_t)bh * Lc * Dh;
    const float* Qp = Q + ((size_t)bh * Lc + q0 + 16 * w) * Dh;

    // ---- Q A-fragments, resident in registers for the whole kernel ----
    uint32_t qa[8][4];
#pragma unroll
    for (int kb = 0; kb < 8; ++kb) {
        qa[kb][0] = f2tf(Qp[(size_t)g * Dh + kb * 8 + q]);
        qa[kb][1] = f2tf(Qp[(size_t)(g + 8) * Dh + kb * 8 + q]);
        qa[kb][2] = f2tf(Qp[(size_t)g * Dh + kb * 8 + q + 4]);
        qa[kb][3] = f2tf(Qp[(size_t)(g + 8) * Dh + kb * 8 + q + 4]);
    }

    float o[8][4];
#pragma unroll
    for (int nb = 0; nb < 8; ++nb)
#pragma unroll
        for (int i = 0; i < 4; ++i) o[nb][i] = 0.f;

    float m0 = -1e30f, m1 = -1e30f, l0 = 0.f, l1 = 0.f;
    const float scale = 0.125f;   // 1/sqrt(64)
    const int row0 = 16 * w + g;  // local tile row of c0/c1
    const int row1 = row0 + 8;    // local tile row of c2/c3

    for (int kv = 0; kv <= qi; ++kv) {
        // ---- stage K,V tiles (tf32-rounded once, at store time) ----
        const float* kp = Kb + (size_t)kv * BN * Dh;
        const float* vp = Vb + (size_t)kv * BN * Dh;
#pragma unroll
        for (int ch = 0; ch < 8; ++ch) {
            int pos = ch * THREADS + t;     // 1024 float4 slots
            int r = pos >> 4;
            int c4 = (pos & 15) << 2;
            float4 kf = *(const float4*)(kp + (size_t)r * Dh + c4);
            kf.x = f2tf_f(kf.x); kf.y = f2tf_f(kf.y);
            kf.z = f2tf_f(kf.z); kf.w = f2tf_f(kf.w);
            *(float4*)(Ks + r * KSTR + c4) = kf;
            float4 vf = *(const float4*)(vp + (size_t)r * Dh + c4);
            vf.x = f2tf_f(vf.x); vf.y = f2tf_f(vf.y);
            vf.z = f2tf_f(vf.z); vf.w = f2tf_f(vf.w);
            *(float4*)(Vs + r * VSTR + c4) = vf;
        }
        __syncthreads();

        // ---- S = Q K^T : 8 n-blocks x 8 k-blocks of m16n8k8 ----
        float s[8][4];
#pragma unroll
        for (int nb = 0; nb < 8; ++nb)
#pragma unroll
            for (int i = 0; i < 4; ++i) s[nb][i] = 0.f;

#pragma unroll
        for (int nb = 0; nb < 8; ++nb) {
            const float* kr = Ks + (nb * 8 + g) * KSTR + q;
#pragma unroll
            for (int kb = 0; kb < 8; ++kb) {
                uint32_t b0 = __float_as_uint(kr[kb * 8]);
                uint32_t b1 = __float_as_uint(kr[kb * 8 + 4]);
                mma_tf32(s[nb], qa[kb], b0, b1);
            }
        }

        // ---- scale + causal mask (diagonal tile only) ----
        const bool diag = (kv == qi);
#pragma unroll
        for (int nb = 0; nb < 8; ++nb) {
            int c0 = 8 * nb + 2 * q;
            s[nb][0] *= scale; s[nb][1] *= scale;
            s[nb][2] *= scale; s[nb][3] *= scale;
            if (diag) {
                if (c0 > row0)     s[nb][0] = -1e30f;
                if (c0 + 1 > row0) s[nb][1] = -1e30f;
                if (c0 > row1)     s[nb][2] = -1e30f;
                if (c0 + 1 > row1) s[nb][3] = -1e30f;
            }
        }

        // ---- online softmax, fully in registers (quad shuffles) ----
        float mx0 = -1e30f, mx1 = -1e30f;
#pragma unroll
        for (int nb = 0; nb < 8; ++nb) {
            mx0 = fmaxf(mx0, fmaxf(s[nb][0], s[nb][1]));
            mx1 = fmaxf(mx1, fmaxf(s[nb][2], s[nb][3]));
        }
        mx0 = fmaxf(mx0, __shfl_xor_sync(0xffffffffu, mx0, 1));
        mx0 = fmaxf(mx0, __shfl_xor_sync(0xffffffffu, mx0, 2));
        mx1 = fmaxf(mx1, __shfl_xor_sync(0xffffffffu, mx1, 1));
        mx1 = fmaxf(mx1, __shfl_xor_sync(0xffffffffu, mx1, 2));

        float mn0 = fmaxf(m0, mx0), mn1 = fmaxf(m1, mx1);
        float a0 = __expf(m0 - mn0), a1 = __expf(m1 - mn1);
        m0 = mn0; m1 = mn1;

        float sum0 = 0.f, sum1 = 0.f;
#pragma unroll
        for (int nb = 0; nb < 8; ++nb) {
            s[nb][0] = __expf(s[nb][0] - m0);
            s[nb][1] = __expf(s[nb][1] - m0);
            s[nb][2] = __expf(s[nb][2] - m1);
            s[nb][3] = __expf(s[nb][3] - m1);
            sum0 += s[nb][0] + s[nb][1];
            sum1 += s[nb][2] + s[nb][3];
        }
        sum0 += __shfl_xor_sync(0xffffffffu, sum0, 1);
        sum0 += __shfl_xor_sync(0xffffffffu, sum0, 2);
        sum1 += __shfl_xor_sync(0xffffffffu, sum1, 1);
        sum1 += __shfl_xor_sync(0xffffffffu, sum1, 2);
        l0 = l0 * a0 + sum0;
        l1 = l1 * a1 + sum1;

        // ---- rescale O ----
#pragma unroll
        for (int nb = 0; nb < 8; ++nb) {
            o[nb][0] *= a0; o[nb][1] *= a0;
            o[nb][2] *= a1; o[nb][3] *= a1;
        }

        // ---- stage P to smem (C-layout -> A-layout relayout, per-warp) ----
        float* pr0 = Ps + row0 * PSTR;
        float* pr1 = Ps + row1 * PSTR;
#pragma unroll
        for (int nb = 0; nb < 8; ++nb) {
            float2 p0 = make_float2(f2tf_f(s[nb][0]), f2tf_f(s[nb][1]));
            float2 p1 = make_float2(f2tf_f(s[nb][2]), f2tf_f(s[nb][3]));
            *(float2*)(pr0 + 8 * nb + 2 * q) = p0;
            *(float2*)(pr1 + 8 * nb + 2 * q) = p1;
        }
        __syncwarp();

        // ---- O += P V : A from Ps (own warp rows), B from Vs ----
#pragma unroll
        for (int kb = 0; kb < 8; ++kb) {
            const float* pp = Ps + row0 * PSTR + kb * 8 + q;
            uint32_t pa[4];
            pa[0] = __float_as_uint(pp[0]);
            pa[1] = __float_as_uint(pp[8 * PSTR]);
            pa[2] = __float_as_uint(pp[4]);
            pa[3] = __float_as_uint(pp[8 * PSTR + 4]);
            const float* vr = Vs + (kb * 8 + q) * VSTR + g;
#pragma unroll
            for (int nb = 0; nb < 8; ++nb) {
                uint32_t b0 = __float_as_uint(vr[nb * 8]);
                uint32_t b1 = __float_as_uint(vr[nb * 8 + 4 * VSTR]);
                mma_tf32(o[nb], pa, b0, b1);
            }
        }
        __syncthreads();   // protect Ks/Vs before next tile load
    }

    // ---- epilogue: normalize + merged-head layout [B, L, H*Dh] ----
    const int b = bh >> 4;
    const int h = bh & 15;
    const float inv0 = 1.f / l0;
    const float inv1 = 1.f / l1;
    float* op0 = O + ((size_t)b * Lc + (q0 + row0)) * (Hc * Dh) + h * Dh;
    float* op1 = O + ((size_t)b * Lc + (q0 + row1)) * (Hc * Dh) + h * Dh;
#pragma unroll
    for (int nb = 0; nb < 8; ++nb) {
        *(float2*)(op0 + 8 * nb + 2 * q) = make_float2(o[nb][0] * inv0, o[nb][1] * inv0);
        *(float2*)(op1 + 8 * nb + 2 * q) = make_float2(o[nb][2] * inv1, o[nb][3] * inv1);
    }
}

}  // namespace

extern "C" void kernel_launch(void* const* d_in, const int* in_sizes, int n_in,
                              void* d_out, int out_size) {
    const float* Q = (const float*)d_in[0];
    const float* K = (const float*)d_in[1];
    const float* V = (const float*)d_in[2];
    float* Out = (float*)d_out;

    cudaFuncSetAttribute(attn_fwd, cudaFuncAttributeMaxDynamicSharedMemorySize, SMEM_BYTES);

    dim3 grid(Lc / BM, Bc * Hc);   // 32 q-tiles x 64 (b,h)
    attn_fwd<<<grid, THREADS, SMEM_BYTES>>>(Q, K, V, Out);
}

// round 3
// speedup vs baseline: 3.5561x; 1.0063x over previous
#include <cuda_runtime.h>
#include <cstdint>

namespace {

constexpr int Bc = 4, Hc = 16, Lc = 2048, Dh = 64;
constexpr int BM = 64;            // q rows per CTA (4 warps x 16)
constexpr int BN = 64;            // kv rows per tile
constexpr int THREADS = 128;
constexpr int KSTR = 64;          // Ks stride: XOR-swizzled, conflict-free B-frag reads
constexpr int VSTR = 72;          // Vs stride: B-frag bank = 8q+g (conflict-free)
constexpr int PSTR = 68;          // Ps stride: A-frag bank = 4g+q (conflict-free)
constexpr int SMEM_FLOATS = BN * KSTR + BN * VSTR + BM * PSTR;
constexpr int SMEM_BYTES = SMEM_FLOATS * (int)sizeof(float);

__device__ __forceinline__ uint32_t f2tf(float f) {
    uint32_t r;
    asm("cvt.rna.tf32.f32 %0, %1;" : "=r"(r) : "f"(f));
    return r;
}
__device__ __forceinline__ float f2tf_f(float f) {
    return __uint_as_float(f2tf(f));
}

__device__ __forceinline__ void mma_tf32(float* c, const uint32_t* a,
                                         uint32_t b0, uint32_t b1) {
    asm volatile(
        "mma.sync.aligned.m16n8k8.row.col.f32.tf32.tf32.f32 "
        "{%0,%1,%2,%3},{%4,%5,%6,%7},{%8,%9},{%0,%1,%2,%3};"
        : "+f"(c[0]), "+f"(c[1]), "+f"(c[2]), "+f"(c[3])
        : "r"(a[0]), "r"(a[1]), "r"(a[2]), "r"(a[3]), "r"(b0), "r"(b1));
}

__global__ void __launch_bounds__(THREADS)
attn_fwd(const float* __restrict__ Q, const float* __restrict__ K,
         const float* __restrict__ V, float* __restrict__ O) {
    extern __shared__ float sm[];
    float* Ks = sm;                  // [64][64] tf32, XOR-swizzled columns
    float* Vs = Ks + BN * KSTR;      // [64][72] tf32
    float* Ps = Vs + BN * VSTR;      // [64][68] tf32 P staging

    const int t = threadIdx.x;
    const int w = t >> 5;            // warp 0..3, owns q rows 16w..16w+15
    const int lane = t & 31;
    const int g = lane >> 2;         // 0..7
    const int q = lane & 3;          // 0..3

    // per-thread constants for swizzled K reads:
    // swizzled col of K[n][8kb+q(+4)] = 8*(kb^gh) + e0 (or e1)
    const int gh = g >> 1;                 // 0..3
    const int e0 = q + ((g & 1) << 2);     // 0..7
    const int e1 = e0 ^ 4;
    int koff[8];
#pragma unroll
    for (int kb = 0; kb < 8; ++kb) koff[kb] = 8 * (kb ^ gh);

    const int bh = blockIdx.y;
    const int qi = (int)gridDim.x - 1 - (int)blockIdx.x;  // big tiles first
    const int q0 = qi * BM;

    const float* Kb = K + (size_t)bh * Lc * Dh;
    const float* Vb = V + (size_t)bh * Lc * Dh;
    const float* Qp = Q + ((size_t)bh * Lc + q0 + 16 * w) * Dh;

    // ---- Q A-fragments (scale folded in), resident in registers ----
    const float scale = 0.125f;   // 1/sqrt(64)
    uint32_t qa[8][4];
#pragma unroll
    for (int kb = 0; kb < 8; ++kb) {
        qa[kb][0] = f2tf(Qp[(size_t)g * Dh + kb * 8 + q] * scale);
        qa[kb][1] = f2tf(Qp[(size_t)(g + 8) * Dh + kb * 8 + q] * scale);
        qa[kb][2] = f2tf(Qp[(size_t)g * Dh + kb * 8 + q + 4] * scale);
        qa[kb][3] = f2tf(Qp[(size_t)(g + 8) * Dh + kb * 8 + q + 4] * scale);
    }

    float o[8][4];
#pragma unroll
    for (int nb = 0; nb < 8; ++nb)
#pragma unroll
        for (int i = 0; i < 4; ++i) o[nb][i] = 0.f;

    float m0 = -1e30f, m1 = -1e30f, l0 = 0.f, l1 = 0.f;
    const int row0 = 16 * w + g;  // local tile row of c0/c1
    const int row1 = row0 + 8;    // local tile row of c2/c3

    for (int kv = 0; kv <= qi; ++kv) {
        // ---- stage K (swizzled), V (padded) tiles, tf32-rounded ----
        const float* kp = Kb + (size_t)kv * BN * Dh;
        const float* vp = Vb + (size_t)kv * BN * Dh;
#pragma unroll
        for (int ch = 0; ch < 8; ++ch) {
            int pos = ch * THREADS + t;     // 1024 float4 slots
            int r = pos >> 4;
            int c4 = (pos & 15) << 2;
            float4 kf = *(const float4*)(kp + (size_t)r * Dh + c4);
            kf.x = f2tf_f(kf.x); kf.y = f2tf_f(kf.y);
            kf.z = f2tf_f(kf.z); kf.w = f2tf_f(kf.w);
            *(float4*)(Ks + r * KSTR + (c4 ^ ((r & 7) << 2))) = kf;
            float4 vf = *(const float4*)(vp + (size_t)r * Dh + c4);
            vf.x = f2tf_f(vf.x); vf.y = f2tf_f(vf.y);
            vf.z = f2tf_f(vf.z); vf.w = f2tf_f(vf.w);
            *(float4*)(Vs + r * VSTR + c4) = vf;
        }
        __syncthreads();

        // ---- S = Q K^T : 8 n-blocks x 8 k-blocks of m16n8k8 ----
        float s[8][4];
#pragma unroll
        for (int nb = 0; nb < 8; ++nb)
#pragma unroll
            for (int i = 0; i < 4; ++i) s[nb][i] = 0.f;

#pragma unroll
        for (int nb = 0; nb < 8; ++nb) {
            const float* kr0 = Ks + (nb * 8 + g) * KSTR + e0;
            const float* kr1 = Ks + (nb * 8 + g) * KSTR + e1;
#pragma unroll
            for (int kb = 0; kb < 8; ++kb) {
                uint32_t b0 = __float_as_uint(kr0[koff[kb]]);
                uint32_t b1 = __float_as_uint(kr1[koff[kb]]);
                mma_tf32(s[nb], qa[kb], b0, b1);
            }
        }

        // ---- causal mask (diagonal tile only; scale already in Q) ----
        const bool diag = (kv == qi);
        if (diag) {
#pragma unroll
            for (int nb = 0; nb < 8; ++nb) {
                int c0 = 8 * nb + 2 * q;
                if (c0 > row0)     s[nb][0] = -1e30f;
                if (c0 + 1 > row0) s[nb][1] = -1e30f;
                if (c0 > row1)     s[nb][2] = -1e30f;
                if (c0 + 1 > row1) s[nb][3] = -1e30f;
            }
        }

        // ---- online softmax, fully in registers (quad shuffles) ----
        float mx0 = -1e30f, mx1 = -1e30f;
#pragma unroll
        for (int nb = 0; nb < 8; ++nb) {
            mx0 = fmaxf(mx0, fmaxf(s[nb][0], s[nb][1]));
            mx1 = fmaxf(mx1, fmaxf(s[nb][2], s[nb][3]));
        }
        mx0 = fmaxf(mx0, __shfl_xor_sync(0xffffffffu, mx0, 1));
        mx0 = fmaxf(mx0, __shfl_xor_sync(0xffffffffu, mx0, 2));
        mx1 = fmaxf(mx1, __shfl_xor_sync(0xffffffffu, mx1, 1));
        mx1 = fmaxf(mx1, __shfl_xor_sync(0xffffffffu, mx1, 2));

        float mn0 = fmaxf(m0, mx0), mn1 = fmaxf(m1, mx1);
        float a0 = __expf(m0 - mn0), a1 = __expf(m1 - mn1);
        m0 = mn0; m1 = mn1;

        float sum0 = 0.f, sum1 = 0.f;
#pragma unroll
        for (int nb = 0; nb < 8; ++nb) {
            s[nb][0] = __expf(s[nb][0] - m0);
            s[nb][1] = __expf(s[nb][1] - m0);
            s[nb][2] = __expf(s[nb][2] - m1);
            s[nb][3] = __expf(s[nb][3] - m1);
            sum0 += s[nb][0] + s[nb][1];
            sum1 += s[nb][2] + s[nb][3];
        }
        sum0 += __shfl_xor_sync(0xffffffffu, sum0, 1);
        sum0 += __shfl_xor_sync(0xffffffffu, sum0, 2);
        sum1 += __shfl_xor_sync(0xffffffffu, sum1, 1);
        sum1 += __shfl_xor_sync(0xffffffffu, sum1, 2);
        l0 = l0 * a0 + sum0;
        l1 = l1 * a1 + sum1;

        // ---- rescale O ----
#pragma unroll
        for (int nb = 0; nb < 8; ++nb) {
            o[nb][0] *= a0; o[nb][1] *= a0;
            o[nb][2] *= a1; o[nb][3] *= a1;
        }

        // ---- stage P to smem (C-layout -> A-layout relayout, per-warp) ----
        float* pr0 = Ps + row0 * PSTR;
        float* pr1 = Ps + row1 * PSTR;
#pragma unroll
        for (int nb = 0; nb < 8; ++nb) {
            float2 p0 = make_float2(f2tf_f(s[nb][0]), f2tf_f(s[nb][1]));
            float2 p1 = make_float2(f2tf_f(s[nb][2]), f2tf_f(s[nb][3]));
            *(float2*)(pr0 + 8 * nb + 2 * q) = p0;
            *(float2*)(pr1 + 8 * nb + 2 * q) = p1;
        }
        __syncwarp();

        // ---- O += P V : A from Ps (own warp rows), B from Vs ----
#pragma unroll
        for (int kb = 0; kb < 8; ++kb) {
            const float* pp = Ps + row0 * PSTR + kb * 8 + q;
            uint32_t pa[4];
            pa[0] = __float_as_uint(pp[0]);
            pa[1] = __float_as_uint(pp[8 * PSTR]);
            pa[2] = __float_as_uint(pp[4]);
            pa[3] = __float_as_uint(pp[8 * PSTR + 4]);
            const float* vr = Vs + (kb * 8 + q) * VSTR + g;
#pragma unroll
            for (int nb = 0; nb < 8; ++nb) {
                uint32_t b0 = __float_as_uint(vr[nb * 8]);
                uint32_t b1 = __float_as_uint(vr[nb * 8 + 4 * VSTR]);
                mma_tf32(o[nb], pa, b0, b1);
            }
        }
        __syncthreads();   // protect Ks/Vs before next tile load
    }

    // ---- epilogue: normalize + merged-head layout [B, L, H*Dh] ----
    const int b = bh >> 4;
    const int h = bh & 15;
    const float inv0 = 1.f / l0;
    const float inv1 = 1.f / l1;
    float* op0 = O + ((size_t)b * Lc + (q0 + row0)) * (Hc * Dh) + h * Dh;
    float* op1 = O + ((size_t)b * Lc + (q0 + row1)) * (Hc * Dh) + h * Dh;
#pragma unroll
    for (int nb = 0; nb < 8; ++nb) {
        *(float2*)(op0 + 8 * nb + 2 * q) = make_float2(o[nb][0] * inv0, o[nb][1] * inv0);
        *(float2*)(op1 + 8 * nb + 2 * q) = make_float2(o[nb][2] * inv1, o[nb][3] * inv1);
    }
}

}  // namespace

extern "C" void kernel_launch(void* const* d_in, const int* in_sizes, int n_in,
                              void* d_out, int out_size) {
    const float* Q = (const float*)d_in[0];
    const float* K = (const float*)d_in[1];
    const float* V = (const float*)d_in[2];
    float* Out = (float*)d_out;

    cudaFuncSetAttribute(attn_fwd, cudaFuncAttributeMaxDynamicSharedMemorySize, SMEM_BYTES);

    dim3 grid(Lc / BM, Bc * Hc);   // 32 q-tiles x 64 (b,h)
    attn_fwd<<<grid, THREADS, SMEM_BYTES>>>(Q, K, V, Out);
}

// round 4
// speedup vs baseline: 5.3485x; 1.5041x over previous
#include <cuda_runtime.h>
#include <cuda_fp16.h>
#include <cstdint>

namespace {

constexpr int Bc = 4, Hc = 16, Lc = 2048, Dh = 64;
constexpr int BM = 64;            // q rows per CTA (4 warps x 16)
constexpr int BN = 64;            // kv rows per tile
constexpr int THREADS = 128;
constexpr int ROWB = 128;         // bytes per smem tile row (64 halves)

__device__ __forceinline__ uint32_t h2u(float a, float b) {
    __half2 h = __floats2half2_rn(a, b);
    return *reinterpret_cast<uint32_t*>(&h);
}

__device__ __forceinline__ void mma16816(float* c, const uint32_t* a,
                                         uint32_t b0, uint32_t b1) {
    asm volatile(
        "mma.sync.aligned.m16n8k16.row.col.f32.f16.f16.f32 "
        "{%0,%1,%2,%3},{%4,%5,%6,%7},{%8,%9},{%0,%1,%2,%3};"
        : "+f"(c[0]), "+f"(c[1]), "+f"(c[2]), "+f"(c[3])
        : "r"(a[0]), "r"(a[1]), "r"(a[2]), "r"(a[3]), "r"(b0), "r"(b1));
}

__device__ __forceinline__ void ldmx4(uint32_t* r, uint32_t addr) {
    asm volatile("ldmatrix.sync.aligned.m8n8.x4.shared.b16 {%0,%1,%2,%3}, [%4];"
                 : "=r"(r[0]), "=r"(r[1]), "=r"(r[2]), "=r"(r[3]) : "r"(addr));
}
__device__ __forceinline__ void ldmx4t(uint32_t* r, uint32_t addr) {
    asm volatile("ldmatrix.sync.aligned.m8n8.x4.trans.shared.b16 {%0,%1,%2,%3}, [%4];"
                 : "=r"(r[0]), "=r"(r[1]), "=r"(r[2]), "=r"(r[3]) : "r"(addr));
}

__global__ void __launch_bounds__(THREADS)
attn_fwd(const float* __restrict__ Q, const float* __restrict__ K,
         const float* __restrict__ V, float* __restrict__ O) {
    // fp16 tiles, 64 rows x 64 halves (128B rows), 16B-chunk XOR swizzle
    __shared__ char Ksm[BN * ROWB];
    __shared__ char Vsm[BN * ROWB];

    const int t = threadIdx.x;
    const int w = t >> 5;            // warp 0..3, owns q rows 16w..16w+15
    const int lane = t & 31;
    const int g = lane >> 2;         // 0..7
    const int q = lane & 3;          // 0..3
    const int ml = lane >> 3;        // 0..3 (ldmatrix matrix id)
    const int rl = lane & 7;         // 0..7 (ldmatrix row within matrix)

    const uint32_t ksm = (uint32_t)__cvta_generic_to_shared(Ksm);
    const uint32_t vsm = (uint32_t)__cvta_generic_to_shared(Vsm);

    const int bh = blockIdx.y;
    const int qi = (int)gridDim.x - 1 - (int)blockIdx.x;  // big tiles first
    const int q0 = qi * BM;

    const float* Kb = K + (size_t)bh * Lc * Dh;
    const float* Vb = V + (size_t)bh * Lc * Dh;
    const float* Qp = Q + ((size_t)bh * Lc + q0 + 16 * w) * Dh;

    // ---- Q A-fragments in fp16 (scale folded), resident in registers ----
    const float scale = 0.125f;   // 1/sqrt(64)
    uint32_t qa[4][4];
#pragma unroll
    for (int kb = 0; kb < 4; ++kb) {
        const float* r0 = Qp + (size_t)g * Dh + 16 * kb + 2 * q;
        const float* r1 = Qp + (size_t)(g + 8) * Dh + 16 * kb + 2 * q;
        qa[kb][0] = h2u(r0[0] * scale, r0[1] * scale);
        qa[kb][1] = h2u(r1[0] * scale, r1[1] * scale);
        qa[kb][2] = h2u(r0[8] * scale, r0[9] * scale);
        qa[kb][3] = h2u(r1[8] * scale, r1[9] * scale);
    }

    float o[8][4];
#pragma unroll
    for (int nb = 0; nb < 8; ++nb)
#pragma unroll
        for (int i = 0; i < 4; ++i) o[nb][i] = 0.f;

    float m0 = -1e30f, m1 = -1e30f, l0 = 0.f, l1 = 0.f;
    const int row0 = 16 * w + g;
    const int row1 = row0 + 8;

    for (int kv = 0; kv <= qi; ++kv) {
        // ---- stage K,V tiles: fp32 global -> fp16 smem, swizzled STS.128 ----
        const float* kp = Kb + (size_t)kv * BN * Dh;
        const float* vp = Vb + (size_t)kv * BN * Dh;
#pragma unroll
        for (int i = 0; i < 4; ++i) {
            int pos = t + THREADS * i;        // 0..511 chunk id
            int r = pos >> 3;                 // row 0..63
            int c = pos & 7;                  // 16B chunk 0..7
            int sw = (c ^ (r & 7)) << 4;      // swizzled byte offset in row
            {
                const float* src = kp + (size_t)r * Dh + c * 8;
                float4 f0 = *(const float4*)src;
                float4 f1 = *(const float4*)(src + 4);
                uint4 u = make_uint4(h2u(f0.x, f0.y), h2u(f0.z, f0.w),
                                     h2u(f1.x, f1.y), h2u(f1.z, f1.w));
                *(uint4*)(Ksm + r * ROWB + sw) = u;
            }
            {
                const float* src = vp + (size_t)r * Dh + c * 8;
                float4 f0 = *(const float4*)src;
                float4 f1 = *(const float4*)(src + 4);
                uint4 u = make_uint4(h2u(f0.x, f0.y), h2u(f0.z, f0.w),
                                     h2u(f1.x, f1.y), h2u(f1.z, f1.w));
                *(uint4*)(Vsm + r * ROWB + sw) = u;
            }
        }
        __syncthreads();

        // ---- S = Q K^T : 8 nb x 4 kb of m16n8k16, B via ldmatrix.x4 ----
        float s[8][4];
#pragma unroll
        for (int nb = 0; nb < 8; ++nb)
#pragma unroll
            for (int i = 0; i < 4; ++i) s[nb][i] = 0.f;

#pragma unroll
        for (int nb = 0; nb < 8; ++nb) {
            uint32_t rowad = ksm + (8 * nb + rl) * ROWB;
#pragma unroll
            for (int kbp = 0; kbp < 2; ++kbp) {
                uint32_t rr[4];
                ldmx4(rr, rowad + ((((kbp << 2) + ml) ^ rl) << 4));
                mma16816(s[nb], qa[2 * kbp],     rr[0], rr[1]);
                mma16816(s[nb], qa[2 * kbp + 1], rr[2], rr[3]);
            }
        }

        // ---- causal mask (diagonal tile only) ----
        if (kv == qi) {
#pragma unroll
            for (int nb = 0; nb < 8; ++nb) {
                int c0 = 8 * nb + 2 * q;
                if (c0 > row0)     s[nb][0] = -1e30f;
                if (c0 + 1 > row0) s[nb][1] = -1e30f;
                if (c0 > row1)     s[nb][2] = -1e30f;
                if (c0 + 1 > row1) s[nb][3] = -1e30f;
            }
        }

        // ---- online softmax, fully in registers ----
        float mx0 = -1e30f, mx1 = -1e30f;
#pragma unroll
        for (int nb = 0; nb < 8; ++nb) {
            mx0 = fmaxf(mx0, fmaxf(s[nb][0], s[nb][1]));
            mx1 = fmaxf(mx1, fmaxf(s[nb][2], s[nb][3]));
        }
        mx0 = fmaxf(mx0, __shfl_xor_sync(0xffffffffu, mx0, 1));
        mx0 = fmaxf(mx0, __shfl_xor_sync(0xffffffffu, mx0, 2));
        mx1 = fmaxf(mx1, __shfl_xor_sync(0xffffffffu, mx1, 1));
        mx1 = fmaxf(mx1, __shfl_xor_sync(0xffffffffu, mx1, 2));

        float mn0 = fmaxf(m0, mx0), mn1 = fmaxf(m1, mx1);
        float a0 = __expf(m0 - mn0), a1 = __expf(m1 - mn1);
        m0 = mn0; m1 = mn1;

        float sum0 = 0.f, sum1 = 0.f;
#pragma unroll
        for (int nb = 0; nb < 8; ++nb) {
            s[nb][0] = __expf(s[nb][0] - m0);
            s[nb][1] = __expf(s[nb][1] - m0);
            s[nb][2] = __expf(s[nb][2] - m1);
            s[nb][3] = __expf(s[nb][3] - m1);
            sum0 += s[nb][0] + s[nb][1];
            sum1 += s[nb][2] + s[nb][3];
        }
        sum0 += __shfl_xor_sync(0xffffffffu, sum0, 1);
        sum0 += __shfl_xor_sync(0xffffffffu, sum0, 2);
        sum1 += __shfl_xor_sync(0xffffffffu, sum1, 1);
        sum1 += __shfl_xor_sync(0xffffffffu, sum1, 2);
        l0 = l0 * a0 + sum0;
        l1 = l1 * a1 + sum1;

        // ---- rescale O ----
#pragma unroll
        for (int nb = 0; nb < 8; ++nb) {
            o[nb][0] *= a0; o[nb][1] *= a0;
            o[nb][2] *= a1; o[nb][3] *= a1;
        }

        // ---- P: C-fragment -> A-fragment conversion IN REGISTERS ----
        uint32_t pa[4][4];
#pragma unroll
        for (int kb = 0; kb < 4; ++kb) {
            pa[kb][0] = h2u(s[2 * kb][0],     s[2 * kb][1]);
            pa[kb][1] = h2u(s[2 * kb][2],     s[2 * kb][3]);
            pa[kb][2] = h2u(s[2 * kb + 1][0], s[2 * kb + 1][1]);
            pa[kb][3] = h2u(s[2 * kb + 1][2], s[2 * kb + 1][3]);
        }

        // ---- O += P V : B via ldmatrix.x4.trans ----
#pragma unroll
        for (int kb = 0; kb < 4; ++kb) {
            uint32_t rowad = vsm + (16 * kb + ((ml & 1) << 3) + rl) * ROWB;
            int swb = ((ml >> 1) ^ rl) << 4;   // chunk (2*nbp + ml>>1) ^ rl, nbp part added below
#pragma unroll
            for (int nbp = 0; nbp < 4; ++nbp) {
                uint32_t rr[4];
                // chunk = 2*nbp + (ml>>1), swizzled with rl
                ldmx4t(rr, rowad + ((((nbp << 1) + (ml >> 1)) ^ rl) << 4));
                mma16816(o[2 * nbp],     pa[kb], rr[0], rr[1]);
                mma16816(o[2 * nbp + 1], pa[kb], rr[2], rr[3]);
            }
            (void)swb;
        }
        __syncthreads();   // protect Ksm/Vsm before next tile load
    }

    // ---- epilogue: normalize + merged-head layout [B, L, H*Dh] ----
    const int b = bh >> 4;
    const int h = bh & 15;
    const float inv0 = 1.f / l0;
    const float inv1 = 1.f / l1;
    float* op0 = O + ((size_t)b * Lc + (q0 + row0)) * (Hc * Dh) + h * Dh;
    float* op1 = O + ((size_t)b * Lc + (q0 + row1)) * (Hc * Dh) + h * Dh;
#pragma unroll
    for (int nb = 0; nb < 8; ++nb) {
        *(float2*)(op0 + 8 * nb + 2 * q) = make_float2(o[nb][0] * inv0, o[nb][1] * inv0);
        *(float2*)(op1 + 8 * nb + 2 * q) = make_float2(o[nb][2] * inv1, o[nb][3] * inv1);
    }
}

}  // namespace

extern "C" void kernel_launch(void* const* d_in, const int* in_sizes, int n_in,
                              void* d_out, int out_size) {
    const float* Q = (const float*)d_in[0];
    const float* K = (const float*)d_in[1];
    const float* V = (const float*)d_in[2];
    float* Out = (float*)d_out;

    dim3 grid(Lc / BM, Bc * Hc);   // 32 q-tiles x 64 (b,h)
    attn_fwd<<<grid, THREADS>>>(Q, K, V, Out);
}

// round 5
// speedup vs baseline: 7.4791x; 1.3983x over previous
#include <cuda_runtime.h>
#include <cuda_fp16.h>
#include <cstdint>

namespace {

constexpr int Bc = 4, Hc = 16, Lc = 2048, Dh = 64;
constexpr int BM = 64;            // q rows per CTA (4 warps x 16)
constexpr int BN = 64;            // kv rows per tile
constexpr int THREADS = 128;
constexpr int ROWB = 128;         // bytes per smem tile row (64 halves)
constexpr int STAGE_B = BN * ROWB;  // 8KB per tile per array
constexpr size_t NELEM = (size_t)Bc * Hc * Lc * Dh;  // 8M elements

__device__ __align__(16) __half KHbuf[NELEM];
__device__ __align__(16) __half VHbuf[NELEM];

__device__ __forceinline__ uint32_t h2u(float a, float b) {
    __half2 h = __floats2half2_rn(a, b);
    return *reinterpret_cast<uint32_t*>(&h);
}

__device__ __forceinline__ float ex2(float x) {
    float r;
    asm("ex2.approx.f32 %0, %1;" : "=f"(r) : "f"(x));
    return r;
}

__device__ __forceinline__ void mma16816(float* c, const uint32_t* a,
                                         uint32_t b0, uint32_t b1) {
    asm volatile(
        "mma.sync.aligned.m16n8k16.row.col.f32.f16.f16.f32 "
        "{%0,%1,%2,%3},{%4,%5,%6,%7},{%8,%9},{%0,%1,%2,%3};"
        : "+f"(c[0]), "+f"(c[1]), "+f"(c[2]), "+f"(c[3])
        : "r"(a[0]), "r"(a[1]), "r"(a[2]), "r"(a[3]), "r"(b0), "r"(b1));
}

__device__ __forceinline__ void ldmx4(uint32_t* r, uint32_t addr) {
    asm volatile("ldmatrix.sync.aligned.m8n8.x4.shared.b16 {%0,%1,%2,%3}, [%4];"
                 : "=r"(r[0]), "=r"(r[1]), "=r"(r[2]), "=r"(r[3]) : "r"(addr));
}
__device__ __forceinline__ void ldmx4t(uint32_t* r, uint32_t addr) {
    asm volatile("ldmatrix.sync.aligned.m8n8.x4.trans.shared.b16 {%0,%1,%2,%3}, [%4];"
                 : "=r"(r[0]), "=r"(r[1]), "=r"(r[2]), "=r"(r[3]) : "r"(addr));
}

__device__ __forceinline__ void cp16(uint32_t dst, const void* src) {
    asm volatile("cp.async.cg.shared.global [%0], [%1], 16;" :: "r"(dst), "l"(src));
}
__device__ __forceinline__ void cp_commit() {
    asm volatile("cp.async.commit_group;");
}
__device__ __forceinline__ void cp_wait_all() {
    asm volatile("cp.async.wait_group 0;");
}

// ---- pre-pass: fp32 K,V -> fp16 scratch ----
__global__ void __launch_bounds__(256)
cvt_kv(const float* __restrict__ K, const float* __restrict__ V) {
    size_t i = ((size_t)blockIdx.x * 256 + threadIdx.x) * 8;
    {
        float4 a = *(const float4*)(K + i);
        float4 b = *(const float4*)(K + i + 4);
        uint4 u = make_uint4(h2u(a.x, a.y), h2u(a.z, a.w), h2u(b.x, b.y), h2u(b.z, b.w));
        *(uint4*)(KHbuf + i) = u;
    }
    {
        float4 a = *(const float4*)(V + i);
        float4 b = *(const float4*)(V + i + 4);
        uint4 u = make_uint4(h2u(a.x, a.y), h2u(a.z, a.w), h2u(b.x, b.y), h2u(b.z, b.w));
        *(uint4*)(VHbuf + i) = u;
    }
}

// issue cp.async for one 64x64 fp16 tile pair (K and V), swizzled
__device__ __forceinline__ void stage_tile(uint32_t kdst, uint32_t vdst,
                                           const __half* kp, const __half* vp, int t) {
#pragma unroll
    for (int i = 0; i < 4; ++i) {
        int pos = t + THREADS * i;        // 0..511
        int r = pos >> 3;                 // row 0..63
        int c = pos & 7;                  // 16B chunk 0..7
        int off = r * ROWB + ((c ^ (r & 7)) << 4);
        cp16(kdst + off, kp + (size_t)r * Dh + c * 8);
        cp16(vdst + off, vp + (size_t)r * Dh + c * 8);
    }
}

__global__ void __launch_bounds__(THREADS)
attn_fwd(const float* __restrict__ Q, float* __restrict__ O) {
    __shared__ char Ksm[2][STAGE_B];
    __shared__ char Vsm[2][STAGE_B];

    const int t = threadIdx.x;
    const int w = t >> 5;            // warp 0..3, owns q rows 16w..16w+15
    const int lane = t & 31;
    const int g = lane >> 2;         // 0..7
    const int q = lane & 3;          // 0..3
    const int ml = lane >> 3;        // 0..3 (ldmatrix matrix id)
    const int rl = lane & 7;         // 0..7 (row within matrix)

    uint32_t ks[2], vs[2];
    ks[0] = (uint32_t)__cvta_generic_to_shared(Ksm[0]);
    ks[1] = (uint32_t)__cvta_generic_to_shared(Ksm[1]);
    vs[0] = (uint32_t)__cvta_generic_to_shared(Vsm[0]);
    vs[1] = (uint32_t)__cvta_generic_to_shared(Vsm[1]);

    const int bh = blockIdx.y;
    const int qi = (int)gridDim.x - 1 - (int)blockIdx.x;  // big tiles first
    const int q0 = qi * BM;

    const __half* Kb = KHbuf + (size_t)bh * Lc * Dh;
    const __half* Vb = VHbuf + (size_t)bh * Lc * Dh;
    const float* Qp = Q + ((size_t)bh * Lc + q0 + 16 * w) * Dh;

    // prologue: stage tile 0
    stage_tile(ks[0], vs[0], Kb, Vb, t);
    cp_commit();

    // ---- Q A-fragments in fp16 (scale*log2e folded), registers ----
    const float scale = 0.125f * 1.44269504088896f;   // 1/sqrt(64) * log2(e)
    uint32_t qa[4][4];
#pragma unroll
    for (int kb = 0; kb < 4; ++kb) {
        const float* r0 = Qp + (size_t)g * Dh + 16 * kb + 2 * q;
        const float* r1 = Qp + (size_t)(g + 8) * Dh + 16 * kb + 2 * q;
        qa[kb][0] = h2u(r0[0] * scale, r0[1] * scale);
        qa[kb][1] = h2u(r1[0] * scale, r1[1] * scale);
        qa[kb][2] = h2u(r0[8] * scale, r0[9] * scale);
        qa[kb][3] = h2u(r1[8] * scale, r1[9] * scale);
    }

    float o[8][4];
#pragma unroll
    for (int nb = 0; nb < 8; ++nb)
#pragma unroll
        for (int i = 0; i < 4; ++i) o[nb][i] = 0.f;

    float m0 = -1e30f, m1 = -1e30f, l0 = 0.f, l1 = 0.f;
    const int row0 = 16 * w + g;
    const int row1 = row0 + 8;

    for (int kv = 0; kv <= qi; ++kv) {
        cp_wait_all();
        __syncthreads();
        const int cur = kv & 1;

        // overlap: stream next tile while computing this one
        if (kv < qi) {
            stage_tile(ks[cur ^ 1], vs[cur ^ 1],
                       Kb + (size_t)(kv + 1) * BN * Dh,
                       Vb + (size_t)(kv + 1) * BN * Dh, t);
            cp_commit();
        }

        // ---- S = Q K^T (logits already in log2 domain) ----
        float s[8][4];
#pragma unroll
        for (int nb = 0; nb < 8; ++nb)
#pragma unroll
            for (int i = 0; i < 4; ++i) s[nb][i] = 0.f;

#pragma unroll
        for (int nb = 0; nb < 8; ++nb) {
            uint32_t rowad = ks[cur] + (8 * nb + rl) * ROWB;
#pragma unroll
            for (int kbp = 0; kbp < 2; ++kbp) {
                uint32_t rr[4];
                ldmx4(rr, rowad + ((((kbp << 2) + ml) ^ rl) << 4));
                mma16816(s[nb], qa[2 * kbp],     rr[0], rr[1]);
                mma16816(s[nb], qa[2 * kbp + 1], rr[2], rr[3]);
            }
        }

        // ---- causal mask (diagonal tile only) ----
        if (kv == qi) {
#pragma unroll
            for (int nb = 0; nb < 8; ++nb) {
                int c0 = 8 * nb + 2 * q;
                if (c0 > row0)     s[nb][0] = -1e30f;
                if (c0 + 1 > row0) s[nb][1] = -1e30f;
                if (c0 > row1)     s[nb][2] = -1e30f;
                if (c0 + 1 > row1) s[nb][3] = -1e30f;
            }
        }

        // ---- online softmax in base-2, fully in registers ----
        float mx0 = -1e30f, mx1 = -1e30f;
#pragma unroll
        for (int nb = 0; nb < 8; ++nb) {
            mx0 = fmaxf(mx0, fmaxf(s[nb][0], s[nb][1]));
            mx1 = fmaxf(mx1, fmaxf(s[nb][2], s[nb][3]));
        }
        mx0 = fmaxf(mx0, __shfl_xor_sync(0xffffffffu, mx0, 1));
        mx0 = fmaxf(mx0, __shfl_xor_sync(0xffffffffu, mx0, 2));
        mx1 = fmaxf(mx1, __shfl_xor_sync(0xffffffffu, mx1, 1));
        mx1 = fmaxf(mx1, __shfl_xor_sync(0xffffffffu, mx1, 2));

        float mn0 = fmaxf(m0, mx0), mn1 = fmaxf(m1, mx1);
        float a0 = ex2(m0 - mn0), a1 = ex2(m1 - mn1);
        m0 = mn0; m1 = mn1;

        float sum0 = 0.f, sum1 = 0.f;
#pragma unroll
        for (int nb = 0; nb < 8; ++nb) {
            s[nb][0] = ex2(s[nb][0] - m0);
            s[nb][1] = ex2(s[nb][1] - m0);
            s[nb][2] = ex2(s[nb][2] - m1);
            s[nb][3] = ex2(s[nb][3] - m1);
            sum0 += s[nb][0] + s[nb][1];
            sum1 += s[nb][2] + s[nb][3];
        }
        sum0 += __shfl_xor_sync(0xffffffffu, sum0, 1);
        sum0 += __shfl_xor_sync(0xffffffffu, sum0, 2);
        sum1 += __shfl_xor_sync(0xffffffffu, sum1, 1);
        sum1 += __shfl_xor_sync(0xffffffffu, sum1, 2);
        l0 = l0 * a0 + sum0;
        l1 = l1 * a1 + sum1;

        // ---- rescale O ----
#pragma unroll
        for (int nb = 0; nb < 8; ++nb) {
            o[nb][0] *= a0; o[nb][1] *= a0;
            o[nb][2] *= a1; o[nb][3] *= a1;
        }

        // ---- P: C-fragment -> A-fragment in registers ----
        uint32_t pa[4][4];
#pragma unroll
        for (int kb = 0; kb < 4; ++kb) {
            pa[kb][0] = h2u(s[2 * kb][0],     s[2 * kb][1]);
            pa[kb][1] = h2u(s[2 * kb][2],     s[2 * kb][3]);
            pa[kb][2] = h2u(s[2 * kb + 1][0], s[2 * kb + 1][1]);
            pa[kb][3] = h2u(s[2 * kb + 1][2], s[2 * kb + 1][3]);
        }

        // ---- O += P V : B via ldmatrix.x4.trans ----
#pragma unroll
        for (int kb = 0; kb < 4; ++kb) {
            uint32_t rowad = vs[cur] + (16 * kb + ((ml & 1) << 3) + rl) * ROWB;
#pragma unroll
            for (int nbp = 0; nbp < 4; ++nbp) {
                uint32_t rr[4];
                ldmx4t(rr, rowad + ((((nbp << 1) + (ml >> 1)) ^ rl) << 4));
                mma16816(o[2 * nbp],     pa[kb], rr[0], rr[1]);
                mma16816(o[2 * nbp + 1], pa[kb], rr[2], rr[3]);
            }
        }
        // no trailing sync: next iteration's top sync precedes buffer reuse
    }

    // ---- epilogue: normalize + merged-head layout [B, L, H*Dh] ----
    const int b = bh >> 4;
    const int h = bh & 15;
    const float inv0 = 1.f / l0;
    const float inv1 = 1.f / l1;
    float* op0 = O + ((size_t)b * Lc + (q0 + row0)) * (Hc * Dh) + h * Dh;
    float* op1 = O + ((size_t)b * Lc + (q0 + row1)) * (Hc * Dh) + h * Dh;
#pragma unroll
    for (int nb = 0; nb < 8; ++nb) {
        *(float2*)(op0 + 8 * nb + 2 * q) = make_float2(o[nb][0] * inv0, o[nb][1] * inv0);
        *(float2*)(op1 + 8 * nb + 2 * q) = make_float2(o[nb][2] * inv1, o[nb][3] * inv1);
    }
}

}  // namespace

extern "C" void kernel_launch(void* const* d_in, const int* in_sizes, int n_in,
                              void* d_out, int out_size) {
    const float* Q = (const float*)d_in[0];
    const float* K = (const float*)d_in[1];
    const float* V = (const float*)d_in[2];
    float* Out = (float*)d_out;

    // pre-pass: K,V -> fp16 scratch (8M elems, 8 per thread)
    cvt_kv<<<(int)(NELEM / (256 * 8)), 256>>>(K, V);

    dim3 grid(Lc / BM, Bc * Hc);   // 32 q-tiles x 64 (b,h)
    attn_fwd<<<grid, THREADS>>>(Q, Out);
}

// round 6
// speedup vs baseline: 8.0490x; 1.0762x over previous
#include <cuda_runtime.h>
#include <cuda_fp16.h>
#include <cstdint>

namespace {

constexpr int Bc = 4, Hc = 16, Lc = 2048, Dh = 64;
constexpr int BM = 128;           // q rows per CTA (4 warps x 32)
constexpr int BN = 64;            // kv rows per tile
constexpr int THREADS = 128;
constexpr int ROWB = 128;         // bytes per smem tile row (64 halves)
constexpr int STAGE_B = BN * ROWB;
constexpr size_t NELEM = (size_t)Bc * Hc * Lc * Dh;  // 8M elements
constexpr uint32_t ONES2 = 0x3C003C00u;              // half2(1,1)

__device__ __align__(16) __half KHbuf[NELEM];
__device__ __align__(16) __half VHbuf[NELEM];

__device__ __forceinline__ uint32_t h2u(float a, float b) {
    __half2 h = __floats2half2_rn(a, b);
    return *reinterpret_cast<uint32_t*>(&h);
}
__device__ __forceinline__ float ex2(float x) {
    float r;
    asm("ex2.approx.f32 %0, %1;" : "=f"(r) : "f"(x));
    return r;
}
__device__ __forceinline__ uint32_t ex2h2(uint32_t x) {
    uint32_t r;
    asm("ex2.approx.f16x2 %0, %1;" : "=r"(r) : "r"(x));
    return r;
}

__device__ __forceinline__ void mma16816(float* c, const uint32_t* a,
                                         uint32_t b0, uint32_t b1) {
    asm volatile(
        "mma.sync.aligned.m16n8k16.row.col.f32.f16.f16.f32 "
        "{%0,%1,%2,%3},{%4,%5,%6,%7},{%8,%9},{%0,%1,%2,%3};"
        : "+f"(c[0]), "+f"(c[1]), "+f"(c[2]), "+f"(c[3])
        : "r"(a[0]), "r"(a[1]), "r"(a[2]), "r"(a[3]), "r"(b0), "r"(b1));
}
__device__ __forceinline__ void ldmx4(uint32_t* r, uint32_t addr) {
    asm volatile("ldmatrix.sync.aligned.m8n8.x4.shared.b16 {%0,%1,%2,%3}, [%4];"
                 : "=r"(r[0]), "=r"(r[1]), "=r"(r[2]), "=r"(r[3]) : "r"(addr));
}
__device__ __forceinline__ void ldmx4t(uint32_t* r, uint32_t addr) {
    asm volatile("ldmatrix.sync.aligned.m8n8.x4.trans.shared.b16 {%0,%1,%2,%3}, [%4];"
                 : "=r"(r[0]), "=r"(r[1]), "=r"(r[2]), "=r"(r[3]) : "r"(addr));
}
__device__ __forceinline__ void cp16(uint32_t dst, const void* src) {
    asm volatile("cp.async.cg.shared.global [%0], [%1], 16;" :: "r"(dst), "l"(src));
}
__device__ __forceinline__ void cp_commit() { asm volatile("cp.async.commit_group;"); }
__device__ __forceinline__ void cp_wait_all() { asm volatile("cp.async.wait_group 0;"); }

// ---- pre-pass: fp32 K,V -> fp16 scratch ----
__global__ void __launch_bounds__(256)
cvt_kv(const float* __restrict__ K, const float* __restrict__ V) {
    size_t i = ((size_t)blockIdx.x * 256 + threadIdx.x) * 8;
    {
        float4 a = *(const float4*)(K + i);
        float4 b = *(const float4*)(K + i + 4);
        *(uint4*)(KHbuf + i) = make_uint4(h2u(a.x, a.y), h2u(a.z, a.w),
                                          h2u(b.x, b.y), h2u(b.z, b.w));
    }
    {
        float4 a = *(const float4*)(V + i);
        float4 b = *(const float4*)(V + i + 4);
        *(uint4*)(VHbuf + i) = make_uint4(h2u(a.x, a.y), h2u(a.z, a.w),
                                          h2u(b.x, b.y), h2u(b.z, b.w));
    }
}

__device__ __forceinline__ void stage_tile(uint32_t kdst, uint32_t vdst,
                                           const __half* kp, const __half* vp, int t) {
#pragma unroll
    for (int i = 0; i < 4; ++i) {
        int pos = t + THREADS * i;        // 0..511
        int r = pos >> 3;
        int c = pos & 7;
        int off = r * ROWB + ((c ^ (r & 7)) << 4);
        cp16(kdst + off, kp + (size_t)r * Dh + c * 8);
        cp16(vdst + off, vp + (size_t)r * Dh + c * 8);
    }
}

__global__ void __launch_bounds__(THREADS, 2)
attn_fwd(const float* __restrict__ Q, float* __restrict__ O) {
    __shared__ char Ksm[2][STAGE_B];
    __shared__ char Vsm[2][STAGE_B];

    const int t = threadIdx.x;
    const int w = t >> 5;            // warp 0..3, owns q rows 32w..32w+31
    const int lane = t & 31;
    const int g = lane >> 2;
    const int q = lane & 3;
    const int ml = lane >> 3;
    const int rl = lane & 7;

    uint32_t ks[2], vs[2];
    ks[0] = (uint32_t)__cvta_generic_to_shared(Ksm[0]);
    ks[1] = (uint32_t)__cvta_generic_to_shared(Ksm[1]);
    vs[0] = (uint32_t)__cvta_generic_to_shared(Vsm[0]);
    vs[1] = (uint32_t)__cvta_generic_to_shared(Vsm[1]);

    const int bh = blockIdx.y;
    const int qt = (int)gridDim.x - 1 - (int)blockIdx.x;  // big tiles first
    const int q0 = qt * BM;
    const int ntiles = 2 * qt + 2;

    const __half* Kb = KHbuf + (size_t)bh * Lc * Dh;
    const __half* Vb = VHbuf + (size_t)bh * Lc * Dh;
    const float* Qp = Q + ((size_t)bh * Lc + q0 + 32 * w) * Dh;

    stage_tile(ks[0], vs[0], Kb, Vb, t);
    cp_commit();

    // ---- Q A-fragments (scale*log2e folded): qa[kb][mf][4] ----
    const float scale = 0.125f * 1.44269504088896f;
    uint32_t qa[4][2][4];
#pragma unroll
    for (int kb = 0; kb < 4; ++kb)
#pragma unroll
        for (int mf = 0; mf < 2; ++mf) {
            const float* r0 = Qp + (size_t)(16 * mf + g) * Dh + 16 * kb + 2 * q;
            const float* r1 = r0 + 8 * Dh;
            qa[kb][mf][0] = h2u(r0[0] * scale, r0[1] * scale);
            qa[kb][mf][1] = h2u(r1[0] * scale, r1[1] * scale);
            qa[kb][mf][2] = h2u(r0[8] * scale, r0[9] * scale);
            qa[kb][mf][3] = h2u(r1[8] * scale, r1[9] * scale);
        }

    float o[2][8][4];
#pragma unroll
    for (int mf = 0; mf < 2; ++mf)
#pragma unroll
        for (int nb = 0; nb < 8; ++nb)
#pragma unroll
            for (int i = 0; i < 4; ++i) o[mf][nb][i] = 0.f;

    float mA[2] = {-1e30f, -1e30f}, mB[2] = {-1e30f, -1e30f};
    float lA[2] = {0.f, 0.f},       lB[2] = {0.f, 0.f};

    for (int kv = 0; kv < ntiles; ++kv) {
        cp_wait_all();
        __syncthreads();
        const int cur = kv & 1;
        if (kv + 1 < ntiles) {
            stage_tile(ks[cur ^ 1], vs[cur ^ 1],
                       Kb + (size_t)(kv + 1) * BN * Dh,
                       Vb + (size_t)(kv + 1) * BN * Dh, t);
            cp_commit();
        }

        // warp fully masked for this tile? (min col > max row)
        if (64 * kv > q0 + 32 * w + 31) continue;

        // ---- S = Q K^T ----
        float s[2][8][4];
#pragma unroll
        for (int mf = 0; mf < 2; ++mf)
#pragma unroll
            for (int nb = 0; nb < 8; ++nb)
#pragma unroll
                for (int i = 0; i < 4; ++i) s[mf][nb][i] = 0.f;

#pragma unroll
        for (int nb = 0; nb < 8; ++nb) {
            uint32_t rowad = ks[cur] + (8 * nb + rl) * ROWB;
#pragma unroll
            for (int kbp = 0; kbp < 2; ++kbp) {
                uint32_t rr[4];
                ldmx4(rr, rowad + ((((kbp << 2) + ml) ^ rl) << 4));
#pragma unroll
                for (int mf = 0; mf < 2; ++mf) {
                    mma16816(s[mf][nb], qa[2 * kbp][mf],     rr[0], rr[1]);
                    mma16816(s[mf][nb], qa[2 * kbp + 1][mf], rr[2], rr[3]);
                }
            }
        }

        // ---- causal mask (edge tiles only) ----
        if (64 * kv + 63 > q0 + 32 * w) {
#pragma unroll
            for (int mf = 0; mf < 2; ++mf) {
                int thrA = q0 + 32 * w + 16 * mf + g - 64 * kv;  // mask col > thrA
                int thrB = thrA + 8;
#pragma unroll
                for (int nb = 0; nb < 8; ++nb) {
                    int c0 = 8 * nb + 2 * q;
                    if (c0 > thrA)     s[mf][nb][0] = -1e30f;
                    if (c0 + 1 > thrA) s[mf][nb][1] = -1e30f;
                    if (c0 > thrB)     s[mf][nb][2] = -1e30f;
                    if (c0 + 1 > thrB) s[mf][nb][3] = -1e30f;
                }
            }
        }

        // ---- softmax (base-2) + P build + PV, per M-fragment ----
        uint32_t pa[2][4][4];
#pragma unroll
        for (int mf = 0; mf < 2; ++mf) {
            float mx0 = -1e30f, mx1 = -1e30f;
#pragma unroll
            for (int nb = 0; nb < 8; ++nb) {
                mx0 = fmaxf(mx0, fmaxf(s[mf][nb][0], s[mf][nb][1]));
                mx1 = fmaxf(mx1, fmaxf(s[mf][nb][2], s[mf][nb][3]));
            }
            mx0 = fmaxf(mx0, __shfl_xor_sync(0xffffffffu, mx0, 1));
            mx0 = fmaxf(mx0, __shfl_xor_sync(0xffffffffu, mx0, 2));
            mx1 = fmaxf(mx1, __shfl_xor_sync(0xffffffffu, mx1, 1));
            mx1 = fmaxf(mx1, __shfl_xor_sync(0xffffffffu, mx1, 2));

            float mnA = fmaxf(mA[mf], mx0), mnB = fmaxf(mB[mf], mx1);
            float aA = ex2(mA[mf] - mnA), aB = ex2(mB[mf] - mnB);
            mA[mf] = mnA; mB[mf] = mnB;
            lA[mf] *= aA; lB[mf] *= aB;

#pragma unroll
            for (int nb = 0; nb < 8; ++nb) {
                o[mf][nb][0] *= aA; o[mf][nb][1] *= aA;
                o[mf][nb][2] *= aB; o[mf][nb][3] *= aB;
            }

            // P in fp16 via packed ex2 (output == A-fragment layout)
#pragma unroll
            for (int kb = 0; kb < 4; ++kb) {
                pa[mf][kb][0] = ex2h2(h2u(s[mf][2 * kb][0] - mnA,     s[mf][2 * kb][1] - mnA));
                pa[mf][kb][1] = ex2h2(h2u(s[mf][2 * kb][2] - mnB,     s[mf][2 * kb][3] - mnB));
                pa[mf][kb][2] = ex2h2(h2u(s[mf][2 * kb + 1][0] - mnA, s[mf][2 * kb + 1][1] - mnA));
                pa[mf][kb][3] = ex2h2(h2u(s[mf][2 * kb + 1][2] - mnB, s[mf][2 * kb + 1][3] - mnB));
            }

            // row sum of P via ones-MMA (exact fp32 sum of the fp16 P)
            float cl[4] = {0.f, 0.f, 0.f, 0.f};
#pragma unroll
            for (int kb = 0; kb < 4; ++kb)
                mma16816(cl, pa[mf][kb], ONES2, ONES2);
            lA[mf] += cl[0];
            lB[mf] += cl[2];
        }

        // ---- O += P V : V frag loaded once, used by both M-frags ----
#pragma unroll
        for (int kb = 0; kb < 4; ++kb) {
            uint32_t rowad = vs[cur] + (16 * kb + ((ml & 1) << 3) + rl) * ROWB;
#pragma unroll
            for (int nbp = 0; nbp < 4; ++nbp) {
                uint32_t rr[4];
                ldmx4t(rr, rowad + ((((nbp << 1) + (ml >> 1)) ^ rl) << 4));
#pragma unroll
                for (int mf = 0; mf < 2; ++mf) {
                    mma16816(o[mf][2 * nbp],     pa[mf][kb], rr[0], rr[1]);
                    mma16816(o[mf][2 * nbp + 1], pa[mf][kb], rr[2], rr[3]);
                }
            }
        }
    }

    // ---- epilogue: normalize + merged-head layout [B, L, H*Dh] ----
    const int b = bh >> 4;
    const int h = bh & 15;
#pragma unroll
    for (int mf = 0; mf < 2; ++mf) {
        int rA = q0 + 32 * w + 16 * mf + g;
        float invA = 1.f / lA[mf];
        float invB = 1.f / lB[mf];
        float* opA = O + ((size_t)b * Lc + rA) * (Hc * Dh) + h * Dh;
        float* opB = opA + (size_t)8 * (Hc * Dh);
#pragma unroll
        for (int nb = 0; nb < 8; ++nb) {
            *(float2*)(opA + 8 * nb + 2 * q) =
                make_float2(o[mf][nb][0] * invA, o[mf][nb][1] * invA);
            *(float2*)(opB + 8 * nb + 2 * q) =
                make_float2(o[mf][nb][2] * invB, o[mf][nb][3] * invB);
        }
    }
}

}  // namespace

extern "C" void kernel_launch(void* const* d_in, const int* in_sizes, int n_in,
                              void* d_out, int out_size) {
    const float* Q = (const float*)d_in[0];
    const float* K = (const float*)d_in[1];
    const float* V = (const float*)d_in[2];
    float* Out = (float*)d_out;

    cvt_kv<<<(int)(NELEM / (256 * 8)), 256>>>(K, V);

    dim3 grid(Lc / BM, Bc * Hc);   // 16 q-tiles x 64 (b,h)
    attn_fwd<<<grid, THREADS>>>(Q, Out);
}

// round 7
// speedup vs baseline: 8.2502x; 1.0250x over previous
#include <cuda_runtime.h>
#include <cuda_fp16.h>
#include <cstdint>

namespace {

constexpr int Bc = 4, Hc = 16, Lc = 2048, Dh = 64;
constexpr int BM = 64;            // q rows per CTA (4 warps x 16)
constexpr int BN = 64;            // kv rows per tile
constexpr int THREADS = 128;
constexpr int ROWB = 128;         // bytes per smem tile row (64 halves)
constexpr int STAGE_B = BN * ROWB;
constexpr size_t NELEM = (size_t)Bc * Hc * Lc * Dh;  // 8M elements
constexpr uint32_t ONES2 = 0x3C003C00u;              // half2(1,1)

__device__ __align__(16) __half KHbuf[NELEM];
__device__ __align__(16) __half VHbuf[NELEM];

__device__ __forceinline__ uint32_t h2u(float a, float b) {
    __half2 h = __floats2half2_rn(a, b);
    return *reinterpret_cast<uint32_t*>(&h);
}
__device__ __forceinline__ float ex2(float x) {
    float r;
    asm("ex2.approx.f32 %0, %1;" : "=f"(r) : "f"(x));
    return r;
}
__device__ __forceinline__ uint32_t ex2h2(uint32_t x) {
    uint32_t r;
    asm("ex2.approx.f16x2 %0, %1;" : "=r"(r) : "r"(x));
    return r;
}

__device__ __forceinline__ void mma16816(float* c, const uint32_t* a,
                                         uint32_t b0, uint32_t b1) {
    asm volatile(
        "mma.sync.aligned.m16n8k16.row.col.f32.f16.f16.f32 "
        "{%0,%1,%2,%3},{%4,%5,%6,%7},{%8,%9},{%0,%1,%2,%3};"
        : "+f"(c[0]), "+f"(c[1]), "+f"(c[2]), "+f"(c[3])
        : "r"(a[0]), "r"(a[1]), "r"(a[2]), "r"(a[3]), "r"(b0), "r"(b1));
}
__device__ __forceinline__ void ldmx4(uint32_t* r, uint32_t addr) {
    asm volatile("ldmatrix.sync.aligned.m8n8.x4.shared.b16 {%0,%1,%2,%3}, [%4];"
                 : "=r"(r[0]), "=r"(r[1]), "=r"(r[2]), "=r"(r[3]) : "r"(addr));
}
__device__ __forceinline__ void ldmx4t(uint32_t* r, uint32_t addr) {
    asm volatile("ldmatrix.sync.aligned.m8n8.x4.trans.shared.b16 {%0,%1,%2,%3}, [%4];"
                 : "=r"(r[0]), "=r"(r[1]), "=r"(r[2]), "=r"(r[3]) : "r"(addr));
}
__device__ __forceinline__ void cp16(uint32_t dst, const void* src) {
    asm volatile("cp.async.cg.shared.global [%0], [%1], 16;" :: "r"(dst), "l"(src));
}
__device__ __forceinline__ void cp_commit() { asm volatile("cp.async.commit_group;"); }
__device__ __forceinline__ void cp_wait_all() { asm volatile("cp.async.wait_group 0;"); }

// ---- pre-pass: fp32 K,V -> fp16 scratch ----
__global__ void __launch_bounds__(256)
cvt_kv(const float* __restrict__ K, const float* __restrict__ V) {
    size_t i = ((size_t)blockIdx.x * 256 + threadIdx.x) * 8;
    {
        float4 a = *(const float4*)(K + i);
        float4 b = *(const float4*)(K + i + 4);
        *(uint4*)(KHbuf + i) = make_uint4(h2u(a.x, a.y), h2u(a.z, a.w),
                                          h2u(b.x, b.y), h2u(b.z, b.w));
    }
    {
        float4 a = *(const float4*)(V + i);
        float4 b = *(const float4*)(V + i + 4);
        *(uint4*)(VHbuf + i) = make_uint4(h2u(a.x, a.y), h2u(a.z, a.w),
                                          h2u(b.x, b.y), h2u(b.z, b.w));
    }
}

__device__ __forceinline__ void stage_tile(uint32_t kdst, uint32_t vdst,
                                           const __half* kp, const __half* vp, int t) {
#pragma unroll
    for (int i = 0; i < 4; ++i) {
        int pos = t + THREADS * i;        // 0..511
        int r = pos >> 3;
        int c = pos & 7;
        int off = r * ROWB + ((c ^ (r & 7)) << 4);
        cp16(kdst + off, kp + (size_t)r * Dh + c * 8);
        cp16(vdst + off, vp + (size_t)r * Dh + c * 8);
    }
}

__global__ void __launch_bounds__(THREADS, 4)
attn_fwd(const float* __restrict__ Q, float* __restrict__ O) {
    __shared__ char Ksm[2][STAGE_B];
    __shared__ char Vsm[2][STAGE_B];

    const int t = threadIdx.x;
    const int w = t >> 5;            // warp 0..3, owns q rows 16w..16w+15
    const int lane = t & 31;
    const int g = lane >> 2;
    const int q = lane & 3;
    const int ml = lane >> 3;
    const int rl = lane & 7;

    uint32_t ks[2], vs[2];
    ks[0] = (uint32_t)__cvta_generic_to_shared(Ksm[0]);
    ks[1] = (uint32_t)__cvta_generic_to_shared(Ksm[1]);
    vs[0] = (uint32_t)__cvta_generic_to_shared(Vsm[0]);
    vs[1] = (uint32_t)__cvta_generic_to_shared(Vsm[1]);

    const int bh = blockIdx.y;
    const int qi = (int)gridDim.x - 1 - (int)blockIdx.x;  // big tiles first
    const int q0 = qi * BM;

    const __half* Kb = KHbuf + (size_t)bh * Lc * Dh;
    const __half* Vb = VHbuf + (size_t)bh * Lc * Dh;
    const float* Qp = Q + ((size_t)bh * Lc + q0 + 16 * w) * Dh;

    stage_tile(ks[0], vs[0], Kb, Vb, t);
    cp_commit();

    // ---- Q A-fragments in fp16 (scale*log2e folded), registers ----
    const float scale = 0.125f * 1.44269504088896f;   // 1/sqrt(64) * log2(e)
    uint32_t qa[4][4];
#pragma unroll
    for (int kb = 0; kb < 4; ++kb) {
        const float* r0 = Qp + (size_t)g * Dh + 16 * kb + 2 * q;
        const float* r1 = r0 + 8 * Dh;
        qa[kb][0] = h2u(r0[0] * scale, r0[1] * scale);
        qa[kb][1] = h2u(r1[0] * scale, r1[1] * scale);
        qa[kb][2] = h2u(r0[8] * scale, r0[9] * scale);
        qa[kb][3] = h2u(r1[8] * scale, r1[9] * scale);
    }

    float o[8][4];
#pragma unroll
    for (int nb = 0; nb < 8; ++nb)
#pragma unroll
        for (int i = 0; i < 4; ++i) o[nb][i] = 0.f;

    float mA = -1e30f, mB = -1e30f, lA = 0.f, lB = 0.f;
    const int row0 = 16 * w + g;
    const int row1 = row0 + 8;

    for (int kv = 0; kv <= qi; ++kv) {
        cp_wait_all();
        __syncthreads();
        const int cur = kv & 1;
        if (kv < qi) {
            stage_tile(ks[cur ^ 1], vs[cur ^ 1],
                       Kb + (size_t)(kv + 1) * BN * Dh,
                       Vb + (size_t)(kv + 1) * BN * Dh, t);
            cp_commit();
        }

        // ---- S = Q K^T (log2 domain) ----
        float s[8][4];
#pragma unroll
        for (int nb = 0; nb < 8; ++nb)
#pragma unroll
            for (int i = 0; i < 4; ++i) s[nb][i] = 0.f;

#pragma unroll
        for (int nb = 0; nb < 8; ++nb) {
            uint32_t rowad = ks[cur] + (8 * nb + rl) * ROWB;
#pragma unroll
            for (int kbp = 0; kbp < 2; ++kbp) {
                uint32_t rr[4];
                ldmx4(rr, rowad + ((((kbp << 2) + ml) ^ rl) << 4));
                mma16816(s[nb], qa[2 * kbp],     rr[0], rr[1]);
                mma16816(s[nb], qa[2 * kbp + 1], rr[2], rr[3]);
            }
        }

        // ---- causal mask (diagonal tile only) ----
        if (kv == qi) {
#pragma unroll
            for (int nb = 0; nb < 8; ++nb) {
                int c0 = 8 * nb + 2 * q;
                if (c0 > row0)     s[nb][0] = -1e30f;
                if (c0 + 1 > row0) s[nb][1] = -1e30f;
                if (c0 > row1)     s[nb][2] = -1e30f;
                if (c0 + 1 > row1) s[nb][3] = -1e30f;
            }
        }

        // ---- online softmax (base-2), fully in registers ----
        float mx0 = -1e30f, mx1 = -1e30f;
#pragma unroll
        for (int nb = 0; nb < 8; ++nb) {
            mx0 = fmaxf(mx0, fmaxf(s[nb][0], s[nb][1]));
            mx1 = fmaxf(mx1, fmaxf(s[nb][2], s[nb][3]));
        }
        mx0 = fmaxf(mx0, __shfl_xor_sync(0xffffffffu, mx0, 1));
        mx0 = fmaxf(mx0, __shfl_xor_sync(0xffffffffu, mx0, 2));
        mx1 = fmaxf(mx1, __shfl_xor_sync(0xffffffffu, mx1, 1));
        mx1 = fmaxf(mx1, __shfl_xor_sync(0xffffffffu, mx1, 2));

        float mnA = fmaxf(mA, mx0), mnB = fmaxf(mB, mx1);
        float aA = ex2(mA - mnA), aB = ex2(mB - mnB);
        mA = mnA; mB = mnB;
        lA *= aA; lB *= aB;

#pragma unroll
        for (int nb = 0; nb < 8; ++nb) {
            o[nb][0] *= aA; o[nb][1] *= aA;
            o[nb][2] *= aB; o[nb][3] *= aB;
        }

        // ---- P in fp16 via packed ex2 (output == A-fragment layout) ----
        uint32_t pa[4][4];
#pragma unroll
        for (int kb = 0; kb < 4; ++kb) {
            pa[kb][0] = ex2h2(h2u(s[2 * kb][0] - mnA,     s[2 * kb][1] - mnA));
            pa[kb][1] = ex2h2(h2u(s[2 * kb][2] - mnB,     s[2 * kb][3] - mnB));
            pa[kb][2] = ex2h2(h2u(s[2 * kb + 1][0] - mnA, s[2 * kb + 1][1] - mnA));
            pa[kb][3] = ex2h2(h2u(s[2 * kb + 1][2] - mnB, s[2 * kb + 1][3] - mnB));
        }

        // ---- row sum of P via ones-MMA ----
        float cl[4] = {0.f, 0.f, 0.f, 0.f};
#pragma unroll
        for (int kb = 0; kb < 4; ++kb)
            mma16816(cl, pa[kb], ONES2, ONES2);
        lA += cl[0];
        lB += cl[2];

        // ---- O += P V : B via ldmatrix.x4.trans ----
#pragma unroll
        for (int kb = 0; kb < 4; ++kb) {
            uint32_t rowad = vs[cur] + (16 * kb + ((ml & 1) << 3) + rl) * ROWB;
#pragma unroll
            for (int nbp = 0; nbp < 4; ++nbp) {
                uint32_t rr[4];
                ldmx4t(rr, rowad + ((((nbp << 1) + (ml >> 1)) ^ rl) << 4));
                mma16816(o[2 * nbp],     pa[kb], rr[0], rr[1]);
                mma16816(o[2 * nbp + 1], pa[kb], rr[2], rr[3]);
            }
        }
    }

    // ---- epilogue: normalize + merged-head layout [B, L, H*Dh] ----
    const int b = bh >> 4;
    const int h = bh & 15;
    const float invA = 1.f / lA;
    const float invB = 1.f / lB;
    float* opA = O + ((size_t)b * Lc + (q0 + row0)) * (Hc * Dh) + h * Dh;
    float* opB = O + ((size_t)b * Lc + (q0 + row1)) * (Hc * Dh) + h * Dh;
#pragma unroll
    for (int nb = 0; nb < 8; ++nb) {
        *(float2*)(opA + 8 * nb + 2 * q) = make_float2(o[nb][0] * invA, o[nb][1] * invA);
        *(float2*)(opB + 8 * nb + 2 * q) = make_float2(o[nb][2] * invB, o[nb][3] * invB);
    }
}

}  // namespace

extern "C" void kernel_launch(void* const* d_in, const int* in_sizes, int n_in,
                              void* d_out, int out_size) {
    const float* Q = (const float*)d_in[0];
    const float* K = (const float*)d_in[1];
    const float* V = (const float*)d_in[2];
    float* Out = (float*)d_out;

    cvt_kv<<<(int)(NELEM / (256 * 8)), 256>>>(K, V);

    dim3 grid(Lc / BM, Bc * Hc);   // 32 q-tiles x 64 (b,h)
    attn_fwd<<<grid, THREADS>>>(Q, Out);
}